// round 7
// baseline (speedup 1.0000x reference)
#include <cuda_runtime.h>

#define NN 512
#define DD 32
#define TT 8192
#define TWO_PI 6.2831853071795864769f
#define INV_TWO_PI 0.15915494309189535f

// ---- packed f32x2 helpers (sm_100+) ----
__device__ __forceinline__ unsigned long long ffma2(unsigned long long a,
                                                    unsigned long long b,
                                                    unsigned long long c) {
    unsigned long long d;
    asm("fma.rn.f32x2 %0, %1, %2, %3;" : "=l"(d) : "l"(a), "l"(b), "l"(c));
    return d;
}
__device__ __forceinline__ unsigned long long pack2(float lo, float hi) {
    unsigned long long r;
    asm("mov.b64 %0, {%1, %2};" : "=l"(r) : "f"(lo), "f"(hi));
    return r;
}
__device__ __forceinline__ void unpack2(unsigned long long v, float& lo, float& hi) {
    asm("mov.b64 {%0, %1}, %2;" : "=f"(lo), "=f"(hi) : "l"(v));
}
__device__ __forceinline__ float wrap2pi(float x) {
    return x - floorf(x * INV_TWO_PI) * TWO_PI;
}
// warp-wide fp32 add reduction via butterfly (redux.f32 not on sm_103)
__device__ __forceinline__ float warp_sum(float v) {
#pragma unroll
    for (int o = 16; o; o >>= 1)
        v += __shfl_xor_sync(0xffffffffu, v, o);
    return v;
}

// complex matvec: acc = sum_d w2[d] * x[d], using 4 accumulators.
// xa layout per d: (xr,xr,xi,xi). Returns (zr,zi).
__device__ __forceinline__ void cmatvec(const unsigned long long* __restrict__ w2,
                                        const float4* __restrict__ xsA,
                                        float& zr, float& zi) {
    unsigned long long a0 = 0ull, a1 = 0ull, b0 = 0ull, b1 = 0ull;
    const ulonglong2* xa = (const ulonglong2*)xsA;
#pragma unroll
    for (int d = 0; d < DD; d += 2) {
        ulonglong2 v0 = xa[d];
        ulonglong2 v1 = xa[d + 1];
        a0 = ffma2(w2[d],     v0.x, a0);   // (Σwr·xr, Σwi·xr)
        b0 = ffma2(w2[d],     v0.y, b0);   // (Σwr·xi, Σwi·xi)
        a1 = ffma2(w2[d + 1], v1.x, a1);
        b1 = ffma2(w2[d + 1], v1.y, b1);
    }
    float a0l, a0h, a1l, a1h, b0l, b0h, b1l, b1h;
    unpack2(a0, a0l, a0h); unpack2(a1, a1l, a1h);
    unpack2(b0, b0l, b0h); unpack2(b1, b1l, b1h);
    float ar = a0l + a1l, ai = a0h + a1h;   // Σwr·xr, Σwi·xr
    float br = b0l + b1l, bi = b0h + b1h;   // Σwr·xi, Σwi·xi
    zr = ar - bi;
    zi = br + ai;
}

__global__ __launch_bounds__(NN, 1)
void rds_kernel(const float* __restrict__ Xr, const float* __restrict__ Xi,
                const float* __restrict__ tw, const float* __restrict__ Wr,
                const float* __restrict__ Wi, const float* __restrict__ phi0,
                const float* __restrict__ beta0, float* __restrict__ out) {
    const int tid  = threadIdx.x;          // neuron index
    const int lane = tid & 31;
    const int wid  = tid >> 5;

    // 4-way buffered per-step shared state
    __shared__ __align__(16) float4 xsA[4][DD];     // (xr,xr,xi,xi) per d
    __shared__ __align__(16) float  xsB[4][2 * DD]; // interleaved (xr,xi)
    __shared__ float  s_tgt[4];
    __shared__ __align__(16) float red[2][16];      // per-warp partial sums

    // W row resident in registers as packed (wr,wi)
    unsigned long long w2[DD];
#pragma unroll
    for (int d = 0; d < DD; d++)
        w2[d] = pack2(Wr[tid * DD + d], Wi[tid * DD + d]);

    float phi  = phi0[tid];
    float beta = beta0[tid];
    float lt   = 0.0f;
    float err  = 0.0f;   // redundant identical scalar chain in every thread

    float* outs   = out;
    float* betas  = out + TT;
    float* gammas = out + TT + (size_t)TT * NN;

    // prologue: load x_0 -> buf0, x_1 -> buf1
    if (tid < DD) {
        float xr = Xr[tid], xi = Xi[tid];
        xsA[0][tid] = make_float4(xr, xr, xi, xi);
        xsB[0][2 * tid] = xr; xsB[0][2 * tid + 1] = xi;
        xr = Xr[DD + tid]; xi = Xi[DD + tid];
        xsA[1][tid] = make_float4(xr, xr, xi, xi);
        xsB[1][2 * tid] = xr; xsB[1][2 * tid + 1] = xi;
        if (tid == 0) { s_tgt[0] = tw[0]; s_tgt[1] = tw[1]; }
    }

    // pipelined head for step 0
    float gamma = __expf(-0.5f * beta);
    float dtl   = gamma * 1e-3f;
    lt += dtl;
    float sn, cs;
    __sincosf(wrap2pi(10.0f * lt + phi), &sn, &cs);

    __syncthreads();

    // Z_0 = W_0 @ x_0 (direct)
    float zr, zi;
    cmatvec(w2, xsA[0], zr, zi);

#pragma unroll 1
    for (int t = 0; t < TT; t++) {
        const int b  = t & 3;
        const int bn = (t + 1) & 3;
        const int bp = (t + 2) & 3;
        const int rb = t & 1;

        // ================= PRE-BARRIER =================
        // gate + contribution (critical: Z -> dot -> butterfly -> STS)
        float dot = cs * zr + sn * zi;    // = |Z| * relu-gated cos(theta-angZ)
        float Y   = fmaxf(dot, 0.0f);
        float v   = warp_sum(Y * cs);
        if (lane == 0) red[rb][wid] = v;

        // prefetch x_{t+2}, tgt_{t+2}
        if (tid < DD && t + 2 < TT) {
            float xr = Xr[(t + 2) * DD + tid];
            float xi = Xi[(t + 2) * DD + tid];
            xsA[bp][tid] = make_float4(xr, xr, xi, xi);
            xsB[bp][2 * tid]     = xr;
            xsB[bp][2 * tid + 1] = xi;
            if (tid == 0) s_tgt[bp] = tw[t + 2];
        }

        // U_t = W_t @ x_{t+1}  (off the scalar critical path)
        float ur, ui;
        cmatvec(w2, xsA[bn], ur, ui);

        // S_t = sum_d x_t[d] * x_{t+1}[d]  (complex; pure-input work)
        float2 c2 = ((const float2*)xsB[b])[lane];
        float2 n2 = ((const float2*)xsB[bn])[lane];
        float sr = warp_sum(c2.x * n2.x - c2.y * n2.y);
        float si = warp_sum(c2.x * n2.y + c2.y * n2.x);

        float tgt = s_tgt[b];

        __syncthreads();   // the single per-step barrier

        // ================= POST-BARRIER =================
        // block total (identical order in every thread)
        float4 r0 = *(const float4*)&red[rb][0];
        float4 r1 = *(const float4*)&red[rb][4];
        float4 r2 = *(const float4*)&red[rb][8];
        float4 r3 = *(const float4*)&red[rb][12];
        float out_v = (((r0.x + r0.y) + (r0.z + r0.w))
                    +  ((r1.x + r1.y) + (r1.z + r1.w)))
                    + (((r2.x + r2.y) + (r2.z + r2.w))
                    +  ((r3.x + r3.y) + (r3.z + r3.w)));

        // thermodynamic feedback
        err = 0.99f * err + 0.01f * fabsf(tgt - out_v);
        float rel  = __fdividef(err, fabsf(tgt) + 0.01f);
        float btgt = 3.5f * __expf(-5.0f * rel);
        float a_s  = (btgt > beta)
                   ? (1.0f - __expf(-2e-3f * (gamma + 1e-6f)))
                   : 0.03278394f;   // 1 - exp(-1/30)
        float bnew = beta + a_s * (btgt - beta);
        bnew = fminf(fmaxf(bnew, 0.005f), 5.0f);

        // W-update coefficients for THIS step
        float gg  = 0.05f * Y * dtl;
        float ddc = bnew * Y * Y * dtl;
        unsigned long long g2  = pack2(gg, gg);
        unsigned long long nd2 = pack2(-ddc, -ddc);

        // Z_{t+1} = (1-ddc)*U + gg*S   (2 FFMA2 -- matvec is off the chain)
        unsigned long long u2 = pack2(ur, ui);
        unsigned long long z2 = ffma2(g2, pack2(sr, si), ffma2(nd2, u2, u2));
        unpack2(z2, zr, zi);

        // outputs
        betas[t * NN + tid]  = bnew;
        gammas[t * NN + tid] = gamma;
        if (tid == 0) outs[t] = out_v;

        // phase pull + wrap
        float phin = phi + (2.0f / 512.0f) * (-tgt * sn) * dtl;
        phin -= floorf(phin * INV_TWO_PI) * TWO_PI;

        // pipelined head of next step (MUFU latency hides under W update)
        float gamman = __expf(-0.5f * bnew);
        float dtln   = gamman * 1e-3f;
        float ltn    = lt + dtln;
        float snn, csn;
        __sincosf(wrap2pi(10.0f * ltn + phin), &snn, &csn);

        // W update: w = (1-ddc)*w + gg*x_t   (needed only by U_{t+1})
        const ulonglong2* xb = (const ulonglong2*)xsB[b];
#pragma unroll
        for (int j = 0; j < DD / 2; j++) {
            ulonglong2 u = xb[j];
            w2[2 * j]     = ffma2(g2, u.x, ffma2(nd2, w2[2 * j],     w2[2 * j]));
            w2[2 * j + 1] = ffma2(g2, u.y, ffma2(nd2, w2[2 * j + 1], w2[2 * j + 1]));
        }

        // rotate pipelined state
        beta  = bnew;
        phi   = phin;
        gamma = gamman;
        dtl   = dtln;
        lt    = ltn;
        sn    = snn;
        cs    = csn;
    }
}

extern "C" void kernel_launch(void* const* d_in, const int* in_sizes, int n_in,
                              void* d_out, int out_size) {
    const float* Xr    = (const float*)d_in[0];
    const float* Xi    = (const float*)d_in[1];
    const float* tw    = (const float*)d_in[2];
    const float* Wr    = (const float*)d_in[3];
    const float* Wi    = (const float*)d_in[4];
    const float* phi0  = (const float*)d_in[5];
    const float* beta0 = (const float*)d_in[6];
    float* out = (float*)d_out;
    rds_kernel<<<1, NN>>>(Xr, Xi, tw, Wr, Wi, phi0, beta0, out);
}